// round 11
// baseline (speedup 1.0000x reference)
#include <cuda_runtime.h>
#include <cfloat>

// Guided directional max pool: out[...,t] = max_{j<=t} x[...,j]*guide[b,0,h,j]
// x [8,256,128,128] fp32, guide [8,1,128,128] fp32.
//
// Block = one quarter of a (b,c) plane: 32 consecutive h rows = 16KB
// contiguous read + 16KB contiguous write. 8 warps x 4 h-iterations,
// one row per warp-iteration (float4 per lane, coalesced). Next iteration's
// x/guide loads are prefetched before the current scan (2 loads always in
// flight). x read-once -> __ldcs; out streamed -> __stcs; guide L2-resident.

#define B_ 8
#define C_ 256
#define H_ 128
#define W_ 128
#define W4 (W_ / 4)

__global__ __launch_bounds__(256, 6)
void i5pool_kernel(const float4* __restrict__ x,
                   const float4* __restrict__ guide,
                   float4* __restrict__ out)
{
    const unsigned lane  = threadIdx.x & 31u;
    const unsigned warp  = threadIdx.x >> 5;
    const unsigned plane = blockIdx.x >> 2;      // b*C + c, 2048 planes
    const unsigned quart = blockIdx.x & 3u;      // which 32-row slab
    const unsigned b     = plane >> 8;           // C == 256

    const float4* xp = x     + (size_t)plane * (H_ * W4);
    float4*       op = out   + (size_t)plane * (H_ * W4);
    const float4* gp = guide + (size_t)b     * (H_ * W4);

    // this warp's rows: h = quart*32 + warp + 8*it, it = 0..3
    unsigned idx = (quart * 32u + warp) * W4 + lane;

    float4 xv = __ldcs(&xp[idx]);
    float4 gv = gp[idx];

    #pragma unroll
    for (int it = 0; it < 4; ++it) {
        const unsigned idx_n = idx + 8u * W4;
        float4 xn, gn;
        if (it < 3) {                     // prefetch next row before scanning
            xn = __ldcs(&xp[idx_n]);
            gn = gp[idx_n];
        }

        // gate (reuse xv as v)
        xv.x *= gv.x;  xv.y *= gv.y;  xv.z *= gv.z;  xv.w *= gv.w;

        // in-lane inclusive cummax
        xv.y = fmaxf(xv.y, xv.x);
        xv.z = fmaxf(xv.z, xv.y);
        xv.w = fmaxf(xv.w, xv.z);

        // warp inclusive max-scan on lane totals
        float t0 = xv.w;
        #pragma unroll
        for (int off = 1; off < 32; off <<= 1) {
            float a = __shfl_up_sync(0xFFFFFFFFu, t0, off);
            if (lane >= (unsigned)off) t0 = fmaxf(t0, a);
        }
        float p = __shfl_up_sync(0xFFFFFFFFu, t0, 1);
        if (lane == 0u) p = -FLT_MAX;

        xv.x = fmaxf(xv.x, p);
        xv.y = fmaxf(xv.y, p);
        xv.z = fmaxf(xv.z, p);
        xv.w = fmaxf(xv.w, p);

        __stcs(&op[idx], xv);

        xv = xn; gv = gn; idx = idx_n;
    }
}

extern "C" void kernel_launch(void* const* d_in, const int* in_sizes, int n_in,
                              void* d_out, int out_size)
{
    const float4* x     = (const float4*)d_in[0];
    const float4* guide = (const float4*)d_in[1];
    float4*       out   = (float4*)d_out;

    // 2048 planes x 4 quarter-slabs = 8192 blocks of 256 threads
    const int blocks = B_ * C_ * 4;
    i5pool_kernel<<<blocks, 256>>>(x, guide, out);
}